// round 15
// baseline (speedup 1.0000x reference)
#include <cuda_runtime.h>
#include <cuda_bf16.h>

// EntNet forward, dead-code-eliminated (see prior rounds).
// R5 big kernels verbatim (best measured). Middle three kernels
// (colpart -> softmax -> u) fused into ONE kernel (k_mid, 256 blocks)
// with 2 sense-reversing grid barriers. 6 -> 4 kernel nodes.
// Co-residency: 256 blocks x 256 thr, <=64 regs -> 2 blocks/SM on 148 SMs.

#define D 4096
#define M 1024
#define L 8192
#define SPLITS 64
#define ROWS_PER 64         // D / SPLITS
#define MIDGRID 256

__device__ float g_sq[D];
__device__ float g_u[D];
__device__ float g_v[D];
__device__ float g_c[M];
__device__ float g_pdot[SPLITS * M];
__device__ float g_pss[SPLITS * M];

__device__ unsigned g_bar_count;
__device__ volatile unsigned g_bar_sense;

__device__ __forceinline__ float warp_reduce_sum(float v) {
#pragma unroll
    for (int o = 16; o > 0; o >>= 1) v += __shfl_down_sync(0xFFFFFFFFu, v, o);
    return v;
}
__device__ __forceinline__ float dot4(float4 a, float4 b) {
    return a.x * b.x + a.y * b.y + a.z * b.z + a.w * b.w;
}
__device__ __forceinline__ float4 ldcs4(const float4* p) { return __ldcs(p); }

// sense-reversing grid barrier over MIDGRID blocks. Two uses per launch:
// sense 0 -> 1 -> 0, so state is replay-clean.
__device__ __forceinline__ void mid_barrier(unsigned want) {
    __syncthreads();
    if (threadIdx.x == 0) {
        __threadfence();
        unsigned old = atomicAdd(&g_bar_count, 1u);
        if (old == MIDGRID - 1) {
            g_bar_count = 0;
            __threadfence();
            g_bar_sense = want;
        } else {
            while (g_bar_sense != want) { }
        }
        __threadfence();
    }
    __syncthreads();
}

// ---------------------------------------------------------------------------
// K1: s_q[d] = dot(F_q[d,:], query) — R5 verbatim
// ---------------------------------------------------------------------------
__global__ __launch_bounds__(256) void k_sq(const float* __restrict__ F,
                                            const float* __restrict__ q) {
    int warp = threadIdx.x >> 5, lane = threadIdx.x & 31;
    int row = blockIdx.x * 8 + warp;
    const float4* Fr = reinterpret_cast<const float4*>(F + (size_t)row * L);
    const float4* q4 = reinterpret_cast<const float4*>(q);
    float a0 = 0.f, a1 = 0.f, a2 = 0.f, a3 = 0.f;
#pragma unroll 4
    for (int k = 0; k < 64; k += 4) {
        int i0 = lane + (k + 0) * 32;
        int i1 = lane + (k + 1) * 32;
        int i2 = lane + (k + 2) * 32;
        int i3 = lane + (k + 3) * 32;
        float4 f0 = ldcs4(&Fr[i0]);
        float4 f1 = ldcs4(&Fr[i1]);
        float4 f2 = ldcs4(&Fr[i2]);
        float4 f3 = ldcs4(&Fr[i3]);
        a0 += dot4(f0, __ldg(&q4[i0]));
        a1 += dot4(f1, __ldg(&q4[i1]));
        a2 += dot4(f2, __ldg(&q4[i2]));
        a3 += dot4(f3, __ldg(&q4[i3]));
    }
    float acc = warp_reduce_sum((a0 + a1) + (a2 + a3));
    if (lane == 0) g_sq[row] = acc;
}

// ---------------------------------------------------------------------------
// K2 (fused middle): colpart (256 blocks) -> barrier -> softmax (block 0)
//                    -> barrier -> u (2 rows/warp)
// ---------------------------------------------------------------------------
__global__ __launch_bounds__(256) void k_mid(const float* __restrict__ mn) {
    int lane = threadIdx.x & 31, warp = threadIdx.x >> 5;

    // ---- P1: column partials. task = blockIdx.x: j-group (4) x slice (64)
    {
        int j = (blockIdx.x & 3) * 256 + threadIdx.x;
        int s = blockIdx.x >> 2;
        __shared__ float shq[ROWS_PER];
        if (threadIdx.x < ROWS_PER) shq[threadIdx.x] = g_sq[s * ROWS_PER + threadIdx.x];
        __syncthreads();

        const float* base = mn + (size_t)s * ROWS_PER * M + j;
        float d0 = 0.f, d1 = 0.f, s0 = 0.f, s1 = 0.f;
#pragma unroll 8
        for (int d = 0; d < ROWS_PER; d += 2) {
            float v0 = base[(size_t)d * M];
            float v1 = base[(size_t)(d + 1) * M];
            d0 += v0 * shq[d];
            d1 += v1 * shq[d + 1];
            s0 += v0 * v0;
            s1 += v1 * v1;
        }
        g_pdot[s * M + j] = d0 + d1;
        g_pss [s * M + j] = s0 + s1;
    }
    mid_barrier(1u);

    // ---- P2: softmax + fold 1/norm (block 0 only; 4 j per thread)
    if (blockIdx.x == 0) {
        float tval[4], nrm[4];
#pragma unroll
        for (int k = 0; k < 4; k++) {
            int j = threadIdx.x + k * 256;
            float dot = 0.f, ss = 0.f;
#pragma unroll
            for (int s = 0; s < SPLITS; ++s) {
                dot += g_pdot[s * M + j];
                ss  += g_pss [s * M + j];
            }
            float n = fmaxf(sqrtf(ss), 1e-12f);
            nrm[k] = n;
            tval[k] = dot / n;
        }
        __shared__ float red[8];
        __shared__ float bcast;

        float m = fmaxf(fmaxf(tval[0], tval[1]), fmaxf(tval[2], tval[3]));
#pragma unroll
        for (int o = 16; o > 0; o >>= 1) m = fmaxf(m, __shfl_down_sync(0xFFFFFFFFu, m, o));
        if (lane == 0) red[warp] = m;
        __syncthreads();
        if (warp == 0) {
            float x = (lane < 8) ? red[lane] : -1e30f;
#pragma unroll
            for (int o = 4; o > 0; o >>= 1) x = fmaxf(x, __shfl_down_sync(0xFFFFFFFFu, x, o));
            if (lane == 0) bcast = x;
        }
        __syncthreads();
        float tmax = bcast;

        float e[4];
        float loc = 0.f;
#pragma unroll
        for (int k = 0; k < 4; k++) { e[k] = expf(tval[k] - tmax); loc += e[k]; }
        float su = warp_reduce_sum(loc);
        __syncthreads();
        if (lane == 0) red[warp] = su;
        __syncthreads();
        if (warp == 0) {
            float x = (lane < 8) ? red[lane] : 0.f;
#pragma unroll
            for (int o = 4; o > 0; o >>= 1) x += __shfl_down_sync(0xFFFFFFFFu, x, o);
            if (lane == 0) bcast = x;
        }
        __syncthreads();
        float esum = bcast;
#pragma unroll
        for (int k = 0; k < 4; k++) {
            int j = threadIdx.x + k * 256;
            g_c[j] = e[k] / (esum * nrm[k]);
        }
    }
    mid_barrier(0u);

    // ---- P3: u = mn @ c. 2048 warps, 2 rows each. mn L2-hot from P1.
    {
        const float4* c4 = reinterpret_cast<const float4*>(g_c);
#pragma unroll
        for (int half = 0; half < 2; half++) {
            int row = blockIdx.x * 8 + warp + half * 2048;
            const float4* r = reinterpret_cast<const float4*>(mn + (size_t)row * M);
            float a0 = 0.f, a1 = 0.f, a2 = 0.f, a3 = 0.f;
            int i0 = lane,       i1 = lane + 32,  i2 = lane + 64,  i3 = lane + 96;
            int i4 = lane + 128, i5 = lane + 160, i6 = lane + 192, i7 = lane + 224;
            float4 m0 = r[i0];
            float4 m1 = r[i1];
            float4 m2 = r[i2];
            float4 m3 = r[i3];
            float4 m4 = r[i4];
            float4 m5 = r[i5];
            float4 m6 = r[i6];
            float4 m7 = r[i7];
            a0 += dot4(m0, __ldg(&c4[i0]));
            a1 += dot4(m1, __ldg(&c4[i1]));
            a2 += dot4(m2, __ldg(&c4[i2]));
            a3 += dot4(m3, __ldg(&c4[i3]));
            a0 += dot4(m4, __ldg(&c4[i4]));
            a1 += dot4(m5, __ldg(&c4[i5]));
            a2 += dot4(m6, __ldg(&c4[i6]));
            a3 += dot4(m7, __ldg(&c4[i7]));
            float acc = warp_reduce_sum((a0 + a1) + (a2 + a3));
            if (lane == 0) g_u[row] = acc;
        }
    }
}

// ---------------------------------------------------------------------------
// K3: v[d] = prelu(s_q[d] + dot(H[d,:], u), a_out) — R5 verbatim
// ---------------------------------------------------------------------------
__global__ __launch_bounds__(256) void k_v(const float* __restrict__ H,
                                           const float* __restrict__ a_out) {
    int warp = threadIdx.x >> 5, lane = threadIdx.x & 31;
    int row = blockIdx.x * 8 + warp;
    const float4* Hr = reinterpret_cast<const float4*>(H + (size_t)row * D);
    const float4* u4 = reinterpret_cast<const float4*>(g_u);
    float a0 = 0.f, a1 = 0.f, a2 = 0.f, a3 = 0.f;
#pragma unroll 4
    for (int k = 0; k < 32; k += 4) {
        int i0 = lane + (k + 0) * 32;
        int i1 = lane + (k + 1) * 32;
        int i2 = lane + (k + 2) * 32;
        int i3 = lane + (k + 3) * 32;
        float4 f0 = ldcs4(&Hr[i0]);
        float4 f1 = ldcs4(&Hr[i1]);
        float4 f2 = ldcs4(&Hr[i2]);
        float4 f3 = ldcs4(&Hr[i3]);
        a0 += dot4(f0, __ldg(&u4[i0]));
        a1 += dot4(f1, __ldg(&u4[i1]));
        a2 += dot4(f2, __ldg(&u4[i2]));
        a3 += dot4(f3, __ldg(&u4[i3]));
    }
    float acc = warp_reduce_sum((a0 + a1) + (a2 + a3));
    if (lane == 0) {
        float x = g_sq[row] + acc;
        float a = __ldg(a_out);
        g_v[row] = (x >= 0.f) ? x : a * x;
    }
}

// ---------------------------------------------------------------------------
// K4: y[d] = dot(R[d,:], v) — R5 verbatim -> d_out
// ---------------------------------------------------------------------------
__global__ __launch_bounds__(256) void k_y(const float* __restrict__ R,
                                           float* __restrict__ out) {
    int warp = threadIdx.x >> 5, lane = threadIdx.x & 31;
    int row = blockIdx.x * 8 + warp;
    const float4* Rr = reinterpret_cast<const float4*>(R + (size_t)row * D);
    const float4* v4 = reinterpret_cast<const float4*>(g_v);
    float a0 = 0.f, a1 = 0.f, a2 = 0.f, a3 = 0.f;
#pragma unroll 4
    for (int k = 0; k < 32; k += 4) {
        int i0 = lane + (k + 0) * 32;
        int i1 = lane + (k + 1) * 32;
        int i2 = lane + (k + 2) * 32;
        int i3 = lane + (k + 3) * 32;
        float4 f0 = ldcs4(&Rr[i0]);
        float4 f1 = ldcs4(&Rr[i1]);
        float4 f2 = ldcs4(&Rr[i2]);
        float4 f3 = ldcs4(&Rr[i3]);
        a0 += dot4(f0, __ldg(&v4[i0]));
        a1 += dot4(f1, __ldg(&v4[i1]));
        a2 += dot4(f2, __ldg(&v4[i2]));
        a3 += dot4(f3, __ldg(&v4[i3]));
    }
    float acc = warp_reduce_sum((a0 + a1) + (a2 + a3));
    if (lane == 0) out[row] = acc;
}

extern "C" void kernel_launch(void* const* d_in, const int* in_sizes, int n_in,
                              void* d_out, int out_size) {
    // metadata order: input, query, F_i, F_q, keys, memory_nodes, U, V, W, R, H, a_mem, a_out
    const float* query = (const float*)d_in[1];
    const float* F_q   = (const float*)d_in[3];
    const float* mn    = (const float*)d_in[5];
    const float* Rm    = (const float*)d_in[9];
    const float* Hm    = (const float*)d_in[10];
    const float* a_out = (const float*)d_in[12];
    float* out = (float*)d_out;

    k_sq<<<D / 8, 256>>>(F_q, query);
    k_mid<<<MIDGRID, 256>>>(mn);
    k_v<<<D / 8, 256>>>(Hm, a_out);
    k_y<<<D / 8, 256>>>(Rm, out);
}

// round 16
// speedup vs baseline: 1.0612x; 1.0612x over previous
#include <cuda_runtime.h>
#include <cuda_bf16.h>

// EntNet forward, dead-code-eliminated (see prior rounds).
// R5 inner loops verbatim (best measured: 65.6us). ONE change: row kernels
// use 128-thread blocks (4 warps) x 1024 blocks instead of 256 x 512.
// All blocks are wave-1 resident either way; 1024 blocks quantize to 7-vs-6
// per SM (1.2% stretch) instead of 4-vs-3 (15.6% stretch).

#define D 4096
#define M 1024
#define L 8192
#define SPLITS 32
#define ROWS_PER 128        // D / SPLITS

__device__ float g_sq[D];
__device__ float g_u[D];
__device__ float g_v[D];
__device__ float g_c[M];
__device__ float g_pdot[SPLITS * M];
__device__ float g_pss[SPLITS * M];

__device__ __forceinline__ float warp_reduce_sum(float v) {
#pragma unroll
    for (int o = 16; o > 0; o >>= 1) v += __shfl_down_sync(0xFFFFFFFFu, v, o);
    return v;
}
__device__ __forceinline__ float dot4(float4 a, float4 b) {
    return a.x * b.x + a.y * b.y + a.z * b.z + a.w * b.w;
}
__device__ __forceinline__ float4 ldcs4(const float4* p) { return __ldcs(p); }

// ---------------------------------------------------------------------------
// K1: s_q[d] = dot(F_q[d,:], query) — warp-per-row, 64 f4/lane
// 1024 blocks x 128 thr (4 rows/block)
// ---------------------------------------------------------------------------
__global__ __launch_bounds__(128) void k_sq(const float* __restrict__ F,
                                            const float* __restrict__ q) {
    int warp = threadIdx.x >> 5, lane = threadIdx.x & 31;
    int row = blockIdx.x * 4 + warp;
    const float4* Fr = reinterpret_cast<const float4*>(F + (size_t)row * L);
    const float4* q4 = reinterpret_cast<const float4*>(q);
    float a0 = 0.f, a1 = 0.f, a2 = 0.f, a3 = 0.f;
#pragma unroll 4
    for (int k = 0; k < 64; k += 4) {
        int i0 = lane + (k + 0) * 32;
        int i1 = lane + (k + 1) * 32;
        int i2 = lane + (k + 2) * 32;
        int i3 = lane + (k + 3) * 32;
        float4 f0 = ldcs4(&Fr[i0]);
        float4 f1 = ldcs4(&Fr[i1]);
        float4 f2 = ldcs4(&Fr[i2]);
        float4 f3 = ldcs4(&Fr[i3]);
        a0 += dot4(f0, __ldg(&q4[i0]));
        a1 += dot4(f1, __ldg(&q4[i1]));
        a2 += dot4(f2, __ldg(&q4[i2]));
        a3 += dot4(f3, __ldg(&q4[i3]));
    }
    float acc = warp_reduce_sum((a0 + a1) + (a2 + a3));
    if (lane == 0) g_sq[row] = acc;
}

// ---------------------------------------------------------------------------
// K2: per-column partial dot(s_q, mn[:,j]) and sum-of-squares over a D-slice.
// (R5 verbatim; warms L2 with mn for k_u)
// ---------------------------------------------------------------------------
__global__ __launch_bounds__(256) void k_colpart(const float* __restrict__ mn) {
    int j = blockIdx.x * 256 + threadIdx.x;   // 4 x-blocks cover M=1024
    int s = blockIdx.y;                       // 32 slices of 128 rows
    __shared__ float shq[ROWS_PER];
    if (threadIdx.x < ROWS_PER) shq[threadIdx.x] = g_sq[s * ROWS_PER + threadIdx.x];
    __syncthreads();

    const float* base = mn + (size_t)s * ROWS_PER * M + j;
    float d0 = 0.f, d1 = 0.f, s0 = 0.f, s1 = 0.f;
#pragma unroll 8
    for (int d = 0; d < ROWS_PER; d += 2) {
        float v0 = base[(size_t)d * M];
        float v1 = base[(size_t)(d + 1) * M];
        d0 += v0 * shq[d];
        d1 += v1 * shq[d + 1];
        s0 += v0 * v0;
        s1 += v1 * v1;
    }
    g_pdot[s * M + j] = d0 + d1;
    g_pss [s * M + j] = s0 + s1;
}

// ---------------------------------------------------------------------------
// K3: reduce partials, softmax over M, fold 1/norm into c_j = p_j / ||mn_j||.
// (R5 verbatim)
// ---------------------------------------------------------------------------
__global__ __launch_bounds__(1024) void k_softmax() {
    int j = threadIdx.x;
    float dot = 0.f, ss = 0.f;
#pragma unroll
    for (int s = 0; s < SPLITS; ++s) {
        dot += g_pdot[s * M + j];
        ss  += g_pss [s * M + j];
    }
    float norm = fmaxf(sqrtf(ss), 1e-12f);
    float t = dot / norm;

    __shared__ float red[32];
    __shared__ float bcast;
    int lane = j & 31, wid = j >> 5;

    float m = t;
#pragma unroll
    for (int o = 16; o > 0; o >>= 1) m = fmaxf(m, __shfl_down_sync(0xFFFFFFFFu, m, o));
    if (lane == 0) red[wid] = m;
    __syncthreads();
    if (wid == 0) {
        float x = red[lane];
#pragma unroll
        for (int o = 16; o > 0; o >>= 1) x = fmaxf(x, __shfl_down_sync(0xFFFFFFFFu, x, o));
        if (lane == 0) bcast = x;
    }
    __syncthreads();
    float tmax = bcast;

    float e = expf(t - tmax);

    float su = warp_reduce_sum(e);
    __syncthreads();
    if (lane == 0) red[wid] = su;
    __syncthreads();
    if (wid == 0) {
        float x = red[lane];
        x = warp_reduce_sum(x);
        if (lane == 0) bcast = x;
    }
    __syncthreads();
    float esum = bcast;

    g_c[j] = e / (esum * norm);
}

// ---------------------------------------------------------------------------
// K4: u[d] = dot(mn[d,:], c) — warp-per-row, 1024 blocks x 128 thr, mn L2-hot
// ---------------------------------------------------------------------------
__global__ __launch_bounds__(128) void k_u(const float* __restrict__ mn) {
    int warp = threadIdx.x >> 5, lane = threadIdx.x & 31;
    int row = blockIdx.x * 4 + warp;
    const float4* r  = reinterpret_cast<const float4*>(mn + (size_t)row * M);
    const float4* c4 = reinterpret_cast<const float4*>(g_c);
    float a0 = 0.f, a1 = 0.f, a2 = 0.f, a3 = 0.f;
    int i0 = lane,       i1 = lane + 32,  i2 = lane + 64,  i3 = lane + 96;
    int i4 = lane + 128, i5 = lane + 160, i6 = lane + 192, i7 = lane + 224;
    float4 m0 = r[i0];
    float4 m1 = r[i1];
    float4 m2 = r[i2];
    float4 m3 = r[i3];
    float4 m4 = r[i4];
    float4 m5 = r[i5];
    float4 m6 = r[i6];
    float4 m7 = r[i7];
    a0 += dot4(m0, __ldg(&c4[i0]));
    a1 += dot4(m1, __ldg(&c4[i1]));
    a2 += dot4(m2, __ldg(&c4[i2]));
    a3 += dot4(m3, __ldg(&c4[i3]));
    a0 += dot4(m4, __ldg(&c4[i4]));
    a1 += dot4(m5, __ldg(&c4[i5]));
    a2 += dot4(m6, __ldg(&c4[i6]));
    a3 += dot4(m7, __ldg(&c4[i7]));
    float acc = warp_reduce_sum((a0 + a1) + (a2 + a3));
    if (lane == 0) g_u[row] = acc;
}

// ---------------------------------------------------------------------------
// K5: v[d] = prelu(s_q[d] + dot(H[d,:], u), a_out) — 1024 blocks x 128 thr
// ---------------------------------------------------------------------------
__global__ __launch_bounds__(128) void k_v(const float* __restrict__ H,
                                           const float* __restrict__ a_out) {
    int warp = threadIdx.x >> 5, lane = threadIdx.x & 31;
    int row = blockIdx.x * 4 + warp;
    const float4* Hr = reinterpret_cast<const float4*>(H + (size_t)row * D);
    const float4* u4 = reinterpret_cast<const float4*>(g_u);
    float a0 = 0.f, a1 = 0.f, a2 = 0.f, a3 = 0.f;
#pragma unroll 4
    for (int k = 0; k < 32; k += 4) {
        int i0 = lane + (k + 0) * 32;
        int i1 = lane + (k + 1) * 32;
        int i2 = lane + (k + 2) * 32;
        int i3 = lane + (k + 3) * 32;
        float4 f0 = ldcs4(&Hr[i0]);
        float4 f1 = ldcs4(&Hr[i1]);
        float4 f2 = ldcs4(&Hr[i2]);
        float4 f3 = ldcs4(&Hr[i3]);
        a0 += dot4(f0, __ldg(&u4[i0]));
        a1 += dot4(f1, __ldg(&u4[i1]));
        a2 += dot4(f2, __ldg(&u4[i2]));
        a3 += dot4(f3, __ldg(&u4[i3]));
    }
    float acc = warp_reduce_sum((a0 + a1) + (a2 + a3));
    if (lane == 0) {
        float x = g_sq[row] + acc;
        float a = __ldg(a_out);
        g_v[row] = (x >= 0.f) ? x : a * x;
    }
}

// ---------------------------------------------------------------------------
// K6: y[d] = dot(R[d,:], v) — 1024 blocks x 128 thr -> d_out
// ---------------------------------------------------------------------------
__global__ __launch_bounds__(128) void k_y(const float* __restrict__ R,
                                           float* __restrict__ out) {
    int warp = threadIdx.x >> 5, lane = threadIdx.x & 31;
    int row = blockIdx.x * 4 + warp;
    const float4* Rr = reinterpret_cast<const float4*>(R + (size_t)row * D);
    const float4* v4 = reinterpret_cast<const float4*>(g_v);
    float a0 = 0.f, a1 = 0.f, a2 = 0.f, a3 = 0.f;
#pragma unroll 4
    for (int k = 0; k < 32; k += 4) {
        int i0 = lane + (k + 0) * 32;
        int i1 = lane + (k + 1) * 32;
        int i2 = lane + (k + 2) * 32;
        int i3 = lane + (k + 3) * 32;
        float4 f0 = ldcs4(&Rr[i0]);
        float4 f1 = ldcs4(&Rr[i1]);
        float4 f2 = ldcs4(&Rr[i2]);
        float4 f3 = ldcs4(&Rr[i3]);
        a0 += dot4(f0, __ldg(&v4[i0]));
        a1 += dot4(f1, __ldg(&v4[i1]));
        a2 += dot4(f2, __ldg(&v4[i2]));
        a3 += dot4(f3, __ldg(&v4[i3]));
    }
    float acc = warp_reduce_sum((a0 + a1) + (a2 + a3));
    if (lane == 0) out[row] = acc;
}

extern "C" void kernel_launch(void* const* d_in, const int* in_sizes, int n_in,
                              void* d_out, int out_size) {
    // metadata order: input, query, F_i, F_q, keys, memory_nodes, U, V, W, R, H, a_mem, a_out
    const float* query = (const float*)d_in[1];
    const float* F_q   = (const float*)d_in[3];
    const float* mn    = (const float*)d_in[5];
    const float* Rm    = (const float*)d_in[9];
    const float* Hm    = (const float*)d_in[10];
    const float* a_out = (const float*)d_in[12];
    float* out = (float*)d_out;

    k_sq<<<D / 4, 128>>>(F_q, query);
    dim3 g2(M / 256, SPLITS);
    k_colpart<<<g2, 256>>>(mn);
    k_softmax<<<1, 1024>>>();
    k_u<<<D / 4, 128>>>(mn);
    k_v<<<D / 4, 128>>>(Hm, a_out);
    k_y<<<D / 4, 128>>>(Rm, out);
}